// round 1
// baseline (speedup 1.0000x reference)
#include <cuda_runtime.h>
#include <cuda_bf16.h>
#include <math.h>

// Problem constants
#define BB 16
#define CC 256
#define LL 2048

// Scratch (alloc-free rule: __device__ globals)
__device__ float g_scores_c[(size_t)BB * CC * CC];            // 4 MB
__device__ float g_yc[(size_t)BB * CC * LL];                  // 32 MB
__device__ float g_scores_t[(size_t)BB * LL * LL];            // 256 MB

#define BM 64
#define BN 64
#define BK 16
#define PAD 4   // 16B-aligned row stride (68 floats) -> LDS.128-able compute reads

// Layouts:
//  AT=false : A[m*lda + k]  (MK)     AT=true : A[k*lda + m] (KM)
//  BT=false : B[k*ldb + n]  (KN)     BT=true : B[n*ldb + k] (NK)
// EPI=false: C = scale * acc
// EPI=true : C = (*beta_p)*acc + (*alpha_p)*yc[idx] + (*gamma_p)*yres[idx]
template<bool AT, bool BT, bool EPI>
__global__ __launch_bounds__(256)
void gemm_k(const float* __restrict__ Ag, size_t sA,
            const float* __restrict__ Bg, size_t sB,
            float* __restrict__ Cg, size_t sC,
            int lda, int ldb, int ldc, int K,
            float scale,
            const float* __restrict__ yc, const float* __restrict__ yres, size_t sAdd,
            const float* __restrict__ alpha_p, const float* __restrict__ beta_p,
            const float* __restrict__ gamma_p)
{
    __shared__ float As[BK][BM + PAD];
    __shared__ float Bs[BK][BN + PAD];

    const float* A = Ag + (size_t)blockIdx.z * sA;
    const float* B = Bg + (size_t)blockIdx.z * sB;
    float*       C = Cg + (size_t)blockIdx.z * sC;

    const int tid = threadIdx.x;
    const int tx  = tid & 15;   // 0..15 -> 4 cols each
    const int ty  = tid >> 4;   // 0..15 -> 4 rows each
    const int row0 = blockIdx.y * BM;
    const int col0 = blockIdx.x * BN;

    float acc[4][4] = {};

    for (int k0 = 0; k0 < K; k0 += BK) {
        // ---- load A tile into As[k][m] ----
        if (AT) {
            int m  = tid & 63;
            int kk = tid >> 6;          // 0..3
            #pragma unroll
            for (int j = 0; j < 4; j++)
                As[kk + 4*j][m] = A[(size_t)(k0 + kk + 4*j) * lda + (row0 + m)];
        } else {
            int kk = tid & 15;
            int m  = tid >> 4;          // 0..15
            #pragma unroll
            for (int j = 0; j < 4; j++)
                As[kk][m + 16*j] = A[(size_t)(row0 + m + 16*j) * lda + (k0 + kk)];
        }
        // ---- load B tile into Bs[k][n] ----
        if (!BT) {
            int n  = tid & 63;
            int kk = tid >> 6;
            #pragma unroll
            for (int j = 0; j < 4; j++)
                Bs[kk + 4*j][n] = B[(size_t)(k0 + kk + 4*j) * ldb + (col0 + n)];
        } else {
            int kk = tid & 15;
            int n  = tid >> 4;
            #pragma unroll
            for (int j = 0; j < 4; j++)
                Bs[kk][n + 16*j] = B[(size_t)(col0 + n + 16*j) * ldb + (k0 + kk)];
        }
        __syncthreads();

        #pragma unroll
        for (int kk = 0; kk < BK; kk++) {
            float a[4], b[4];
            #pragma unroll
            for (int i = 0; i < 4; i++) a[i] = As[kk][ty*4 + i];
            #pragma unroll
            for (int i = 0; i < 4; i++) b[i] = Bs[kk][tx*4 + i];
            #pragma unroll
            for (int i = 0; i < 4; i++)
                #pragma unroll
                for (int j = 0; j < 4; j++)
                    acc[i][j] = fmaf(a[i], b[j], acc[i][j]);
        }
        __syncthreads();
    }

    if (EPI) {
        const float al = *alpha_p, be = *beta_p, ga = *gamma_p;
        const float* ycb = yc   + (size_t)blockIdx.z * sAdd;
        const float* yrb = yres + (size_t)blockIdx.z * sAdd;
        #pragma unroll
        for (int i = 0; i < 4; i++) {
            size_t base = (size_t)(row0 + ty*4 + i) * ldc + (col0 + tx*4);
            #pragma unroll
            for (int j = 0; j < 4; j++)
                C[base + j] = be * acc[i][j] + al * ycb[base + j] + ga * yrb[base + j];
        }
    } else {
        #pragma unroll
        for (int i = 0; i < 4; i++) {
            size_t base = (size_t)(row0 + ty*4 + i) * ldc + (col0 + tx*4);
            #pragma unroll
            for (int j = 0; j < 4; j++)
                C[base + j] = scale * acc[i][j];
        }
    }
}

// In-place row softmax, one block per row.
__global__ __launch_bounds__(256)
void softmax_rows_k(float* __restrict__ data, int cols)
{
    float* row = data + (size_t)blockIdx.x * (size_t)cols;
    __shared__ float red[32];
    __shared__ float bcast;
    const int tid  = threadIdx.x;
    const int lane = tid & 31;
    const int warp = tid >> 5;
    const int nw   = blockDim.x >> 5;

    float m = -3.4e38f;
    for (int i = tid; i < cols; i += blockDim.x) m = fmaxf(m, row[i]);
    #pragma unroll
    for (int o = 16; o; o >>= 1) m = fmaxf(m, __shfl_xor_sync(0xffffffffu, m, o));
    if (lane == 0) red[warp] = m;
    __syncthreads();
    if (warp == 0) {
        float v = (lane < nw) ? red[lane] : -3.4e38f;
        #pragma unroll
        for (int o = 16; o; o >>= 1) v = fmaxf(v, __shfl_xor_sync(0xffffffffu, v, o));
        if (lane == 0) bcast = v;
    }
    __syncthreads();
    m = bcast;

    float s = 0.f;
    for (int i = tid; i < cols; i += blockDim.x) {
        float e = expf(row[i] - m);
        row[i] = e;
        s += e;
    }
    #pragma unroll
    for (int o = 16; o; o >>= 1) s += __shfl_xor_sync(0xffffffffu, s, o);
    if (lane == 0) red[warp] = s;
    __syncthreads();
    if (warp == 0) {
        float v = (lane < nw) ? red[lane] : 0.f;
        #pragma unroll
        for (int o = 16; o; o >>= 1) v += __shfl_xor_sync(0xffffffffu, v, o);
        if (lane == 0) bcast = v;
    }
    __syncthreads();
    const float inv = 1.f / bcast;
    for (int i = tid; i < cols; i += blockDim.x) row[i] *= inv;
}

extern "C" void kernel_launch(void* const* d_in, const int* in_sizes, int n_in,
                              void* d_out, int out_size)
{
    const float* y     = (const float*)d_in[0];
    const float* alpha = (const float*)d_in[1];
    const float* beta  = (const float*)d_in[2];
    const float* gamma = (const float*)d_in[3];
    float* out = (float*)d_out;

    float *sc_c, *yc, *sc_t;
    cudaGetSymbolAddress((void**)&sc_c, g_scores_c);
    cudaGetSymbolAddress((void**)&yc,   g_yc);
    cudaGetSymbolAddress((void**)&sc_t, g_scores_t);

    const size_t sY  = (size_t)CC * LL;   // per-batch y stride
    const size_t sSc = (size_t)CC * CC;
    const size_t sSt = (size_t)LL * LL;

    const float scale_c = 1.0f / sqrtf((float)LL);
    const float scale_t = 1.0f / sqrtf((float)CC);

    // 1) scores_c[b][i][j] = scale_c * sum_k y[b][i][k] * y[b][j][k]
    //    A: MK (lda=L), B: NK (ldb=L). M=N=C, K=L.
    gemm_k<false, true, false><<<dim3(CC/BN, CC/BM, BB), 256>>>(
        y, sY, y, sY, sc_c, sSc, LL, LL, CC, LL, scale_c,
        nullptr, nullptr, 0, nullptr, nullptr, nullptr);

    // 2) softmax over last dim (C) of scores_c
    softmax_rows_k<<<BB * CC, 256>>>(sc_c, CC);

    // 3) y_c[b][c][l] = sum_d attn_c[b][c][d] * y[b][d][l]
    //    A: MK (lda=C), B: KN (ldb=L). M=C, N=L, K=C.
    gemm_k<false, false, false><<<dim3(LL/BN, CC/BM, BB), 256>>>(
        sc_c, sSc, y, sY, yc, sY, CC, LL, LL, CC, 1.0f,
        nullptr, nullptr, 0, nullptr, nullptr, nullptr);

    // 4) scores_t[b][l][m] = scale_t * sum_c y[b][c][l] * y[b][c][m]
    //    A: KM (lda=L), B: KN (ldb=L). M=N=L, K=C.
    gemm_k<true, false, false><<<dim3(LL/BN, LL/BM, BB), 256>>>(
        y, sY, y, sY, sc_t, sSt, LL, LL, LL, CC, scale_t,
        nullptr, nullptr, 0, nullptr, nullptr, nullptr);

    // 5) softmax over last dim (L) of scores_t
    softmax_rows_k<<<BB * LL, 256>>>(sc_t, LL);

    // 6) out[b][c][l] = beta * (sum_m y[b][c][m] * attn_t[b][l][m]) + alpha*y_c + gamma*y
    //    A = y: MK (lda=L); B = attn_t: NK (ldb=L). M=C, N=L, K=L. Fused combine epilogue.
    gemm_k<false, true, true><<<dim3(LL/BN, CC/BM, BB), 256>>>(
        y, sY, sc_t, sSt, out, sY, LL, LL, LL, LL, 0.0f,
        yc, y, sY, alpha, beta, gamma);
}